// round 9
// baseline (speedup 1.0000x reference)
#include <cuda_runtime.h>
#include <cuda_fp16.h>
#include <cstdint>

// Inputs (metadata order):
//   0: x        float32 [N=262144]
//   1: Param_W  float32 [1280]
//   2: Param_b  float32 [16]
//   3: w_rows   int32   [E=16777216]
//   4: w_cols   int32   [E]
//   5: w_params int32   [E]
//   6: b_params int32   [N]
// Output: float32 [N]

#define N_NODES 262144

// fp16 copy of x: halves the random-gather footprint (1MB -> 512KB) so the
// L1 capacity-bound hit rate roughly doubles, removing L2-hit wavefronts.
__device__ __half g_xh[N_NODES];

// Fused: out[i] = Param_b[b_params[i]]  AND  g_xh[i] = (half)x[i]
__global__ void prep_kernel(const float* __restrict__ x,
                            const float* __restrict__ Pb,
                            const int* __restrict__ b_params,
                            float* __restrict__ out, int n) {
    int i = blockIdx.x * blockDim.x + threadIdx.x;
    if (i < n) {
        out[i] = __ldg(&Pb[b_params[i]]);
        g_xh[i] = __float2half(x[i]);
    }
}

__global__ void __launch_bounds__(256) edge_scatter_kernel(
    const float* __restrict__ Pw,
    const int4* __restrict__ rows4,
    const int4* __restrict__ cols4,
    const int4* __restrict__ params4,
    float* __restrict__ out,
    int e4) {
    int i = blockIdx.x * blockDim.x + threadIdx.x;
    if (i >= e4) return;

    int4 r = rows4[i];
    int4 c = cols4[i];
    int4 p = params4[i];

    // Fire all x gathers first for MLP; fp16 halves L1 footprint.
    __half h0 = g_xh[c.x];
    __half h1 = g_xh[c.y];
    __half h2 = g_xh[c.z];
    __half h3 = g_xh[c.w];

    // Pw is 5KB -> permanently L1-resident via __ldg.
    float w0 = __ldg(&Pw[p.x]);
    float w1 = __ldg(&Pw[p.y]);
    float w2 = __ldg(&Pw[p.z]);
    float w3 = __ldg(&Pw[p.w]);

    // No-return atomicAdd -> REDG at LTS (184 slices in parallel).
    atomicAdd(&out[r.x], w0 * __half2float(h0));
    atomicAdd(&out[r.y], w1 * __half2float(h1));
    atomicAdd(&out[r.z], w2 * __half2float(h2));
    atomicAdd(&out[r.w], w3 * __half2float(h3));
}

extern "C" void kernel_launch(void* const* d_in, const int* in_sizes, int n_in,
                              void* d_out, int out_size) {
    const float* x        = (const float*)d_in[0];
    const float* Pw       = (const float*)d_in[1];
    const float* Pb       = (const float*)d_in[2];
    const int*   w_rows   = (const int*)d_in[3];
    const int*   w_cols   = (const int*)d_in[4];
    const int*   w_params = (const int*)d_in[5];
    const int*   b_params = (const int*)d_in[6];
    float* out = (float*)d_out;

    int N = out_size;            // 262144
    int E = in_sizes[3];         // 16777216

    // Max-L1 carveout for the gather kernel (it uses no SMEM).
    static int attr_set = 0;
    if (!attr_set) {
        cudaFuncSetAttribute(edge_scatter_kernel,
                             cudaFuncAttributePreferredSharedMemoryCarveout, 0);
        attr_set = 1;
    }

    // 1) bias init + fp16 conversion of x (independent elementwise ops, fused)
    {
        int threads = 256;
        int blocks = (N + threads - 1) / threads;
        prep_kernel<<<blocks, threads>>>(x, Pb, b_params, out, N);
    }

    // 2) scatter-add edges
    {
        int e4 = E / 4;          // E divisible by 4
        int threads = 256;
        int blocks = (e4 + threads - 1) / threads;
        edge_scatter_kernel<<<blocks, threads>>>(
            Pw,
            (const int4*)w_rows, (const int4*)w_cols, (const int4*)w_params,
            out, e4);
    }
}

// round 12
// speedup vs baseline: 1.0210x; 1.0210x over previous
#include <cuda_runtime.h>
#include <cstdint>

// Inputs (metadata order):
//   0: x        float32 [N=262144]
//   1: Param_W  float32 [1280]
//   2: Param_b  float32 [16]
//   3: w_rows   int32   [E=16777216]
//   4: w_cols   int32   [E]
//   5: w_params int32   [E]
//   6: b_params int32   [N]
// Output: float32 [N]

// Vectorized bias init: out[i] = Param_b[b_params[i]], 4 at a time.
__global__ void bias_init_kernel(const float* __restrict__ Pb,
                                 const int4* __restrict__ bp4,
                                 float4* __restrict__ out4, int n4) {
    int i = blockIdx.x * blockDim.x + threadIdx.x;
    if (i < n4) {
        int4 b = bp4[i];
        float4 v;
        v.x = __ldg(&Pb[b.x]);
        v.y = __ldg(&Pb[b.y]);
        v.z = __ldg(&Pb[b.z]);
        v.w = __ldg(&Pb[b.w]);
        out4[i] = v;
    }
}

// 8 edges per thread: two coalesced int4 sweeps per index stream, all 8
// x-gathers issued before any atomic for maximum memory-level parallelism.
// atomicAdd with unused return -> REDG (no-return reduction) at the LTS.
__global__ void __launch_bounds__(256) edge_scatter_kernel(
    const float* __restrict__ x,
    const float* __restrict__ Pw,
    const int4* __restrict__ rows4,
    const int4* __restrict__ cols4,
    const int4* __restrict__ params4,
    float* __restrict__ out,
    int e4) {
    // Two fully-coalesced int4 positions per thread.
    int base = blockIdx.x * (blockDim.x * 2) + threadIdx.x;
    int i0 = base;
    int i1 = base + blockDim.x;
    if (i1 >= e4) {               // tail handling (grid sized so this is rare)
        if (i0 >= e4) return;
        int4 r = rows4[i0], c = cols4[i0], p = params4[i0];
        float x0 = __ldg(&x[c.x]), x1 = __ldg(&x[c.y]);
        float x2 = __ldg(&x[c.z]), x3 = __ldg(&x[c.w]);
        atomicAdd(&out[r.x], __ldg(&Pw[p.x]) * x0);
        atomicAdd(&out[r.y], __ldg(&Pw[p.y]) * x1);
        atomicAdd(&out[r.z], __ldg(&Pw[p.z]) * x2);
        atomicAdd(&out[r.w], __ldg(&Pw[p.w]) * x3);
        return;
    }

    int4 ra = rows4[i0],  rb = rows4[i1];
    int4 ca = cols4[i0],  cb = cols4[i1];
    int4 pa = params4[i0], pb = params4[i1];

    // Fire all 8 x gathers (L2-hit latency, overlapped).
    float xa0 = __ldg(&x[ca.x]);
    float xa1 = __ldg(&x[ca.y]);
    float xa2 = __ldg(&x[ca.z]);
    float xa3 = __ldg(&x[ca.w]);
    float xb0 = __ldg(&x[cb.x]);
    float xb1 = __ldg(&x[cb.y]);
    float xb2 = __ldg(&x[cb.z]);
    float xb3 = __ldg(&x[cb.w]);

    // Pw (5KB) is permanently L1-resident.
    float wa0 = __ldg(&Pw[pa.x]);
    float wa1 = __ldg(&Pw[pa.y]);
    float wa2 = __ldg(&Pw[pa.z]);
    float wa3 = __ldg(&Pw[pa.w]);
    float wb0 = __ldg(&Pw[pb.x]);
    float wb1 = __ldg(&Pw[pb.y]);
    float wb2 = __ldg(&Pw[pb.z]);
    float wb3 = __ldg(&Pw[pb.w]);

    atomicAdd(&out[ra.x], wa0 * xa0);
    atomicAdd(&out[ra.y], wa1 * xa1);
    atomicAdd(&out[ra.z], wa2 * xa2);
    atomicAdd(&out[ra.w], wa3 * xa3);
    atomicAdd(&out[rb.x], wb0 * xb0);
    atomicAdd(&out[rb.y], wb1 * xb1);
    atomicAdd(&out[rb.z], wb2 * xb2);
    atomicAdd(&out[rb.w], wb3 * xb3);
}

extern "C" void kernel_launch(void* const* d_in, const int* in_sizes, int n_in,
                              void* d_out, int out_size) {
    const float* x        = (const float*)d_in[0];
    const float* Pw       = (const float*)d_in[1];
    const float* Pb       = (const float*)d_in[2];
    const int*   w_rows   = (const int*)d_in[3];
    const int*   w_cols   = (const int*)d_in[4];
    const int*   w_params = (const int*)d_in[5];
    const int*   b_params = (const int*)d_in[6];
    float* out = (float*)d_out;

    int N = out_size;            // 262144
    int E = in_sizes[3];         // 16777216

    // 1) out[i] = Param_b[b_params[i]]  (vectorized x4; N divisible by 4)
    {
        int n4 = N / 4;
        int threads = 256;
        int blocks = (n4 + threads - 1) / threads;
        bias_init_kernel<<<blocks, threads>>>(
            Pb, (const int4*)b_params, (float4*)out, n4);
    }

    // 2) scatter-add edges, 8 edges (2 int4 groups) per thread
    {
        int e4 = E / 4;                     // 4194304, divisible by 512
        int threads = 256;
        int groups_per_block = threads * 2; // int4 groups per block
        int blocks = (e4 + groups_per_block - 1) / groups_per_block;
        edge_scatter_kernel<<<blocks, threads>>>(
            x, Pw,
            (const int4*)w_rows, (const int4*)w_cols, (const int4*)w_params,
            out, e4);
    }
}